// round 15
// baseline (speedup 1.0000x reference)
#include <cuda_runtime.h>
#include <math.h>

#define NLEV 16
#define TABLE_SIZE (1u << 19)
#define TMASK (TABLE_SIZE - 1u)
#define PRIME_Y 2654435761u
#define PRIME_Z 805459861u
#define TPB 256
#define STAGES 3

// dense-cache geometry for levels 0..2 (res 16, 20, 25; inputs live in x>=0
// half of the box so bl ranges over [floor(res/2), res-1], corners to res).
#define LO0 8
#define LO1 10
#define LO2 12
#define D0  9
#define D1  11
#define D2  14
#define OFF0 0
#define OFF1 (D0*D0*D0)                    // 729
#define OFF2 (OFF1 + D1*D1*D1)             // 729+1331 = 2060
#define NDENSE (OFF2 + D2*D2*D2)           // 4804
#define STAGE_FLOATS (TPB * 33)
#define SMEM_BYTES (STAGE_FLOATS * 4 + NDENSE * 8)

struct Params { float invg[NLEV]; int cache_ok; };

__device__ float2 g_dense[NDENSE];

// ---- setup kernel: densify levels 0..2 into g_dense ------------------------
__global__ void build_dense(const float* __restrict__ emb)
{
    int i = blockIdx.x * blockDim.x + threadIdx.x;
    if (i >= NDENSE) return;
    int lvl, lo, D, base;
    if (i < OFF1)      { lvl = 0; lo = LO0; D = D0; base = i - OFF0; }
    else if (i < OFF2) { lvl = 1; lo = LO1; D = D1; base = i - OFF1; }
    else               { lvl = 2; lo = LO2; D = D2; base = i - OFF2; }
    int iz = base % D; int t = base / D; int iy = t % D; int ix = t / D;
    unsigned h = ((unsigned)(ix + lo)
                  ^ ((unsigned)(iy + lo) * PRIME_Y)
                  ^ ((unsigned)(iz + lo) * PRIME_Z)) & TMASK;
    const float2* tab = (const float2*)emb + (size_t)lvl * TABLE_SIZE;
    g_dense[i] = __ldg(&tab[h]);
}

// ---- LDG load phase (levels 3..15 + fallback) ------------------------------
// PRIME_X == 1: even bl.x -> corner pair (h, h^1) = one aligned float4 load.
__device__ __forceinline__ void load_level(
    const float* __restrict__ emb, int lvl, float invg,
    float X0, float X1, float X2,
    float4 e[4], unsigned& meta4, float& w0, float& w1, float& w2)
{
    const float t0 = X0 * invg, t1 = X1 * invg, t2 = X2 * invg;
    const float f0 = floorf(t0), f1 = floorf(t1), f2 = floorf(t2);
    w0 = t0 - f0; w1 = t1 - f1; w2 = t2 - f2;

    const unsigned hx = (unsigned)(int)f0;
    const unsigned hy = (unsigned)(int)f1 * PRIME_Y;
    const unsigned hz = (unsigned)(int)f2 * PRIME_Z;
    const unsigned r0 = hy ^ hz;
    const unsigned r1 = hy ^ (hz + PRIME_Z);
    const unsigned r2 = (hy + PRIME_Y) ^ hz;
    const unsigned r3 = (hy + PRIME_Y) ^ (hz + PRIME_Z);
    const unsigned h0 = (hx ^ r0) & TMASK, h1 = (hx ^ r1) & TMASK;
    const unsigned h2 = (hx ^ r2) & TMASK, h3 = (hx ^ r3) & TMASK;

    const float2* tab2 = (const float2*)emb + (size_t)lvl * TABLE_SIZE;
    const float4* tab4 = (const float4*)tab2;

    if ((hx & 1u) == 0u) {
        e[0] = __ldg(&tab4[h0 >> 1]);
        e[1] = __ldg(&tab4[h1 >> 1]);
        e[2] = __ldg(&tab4[h2 >> 1]);
        e[3] = __ldg(&tab4[h3 >> 1]);
        meta4 = (h0 & 1u) | ((h1 & 1u) << 1) | ((h2 & 1u) << 2) | ((h3 & 1u) << 3);
    } else {
        const unsigned hx1 = hx + 1u;
        const unsigned g0 = (hx1 ^ r0) & TMASK, g1 = (hx1 ^ r1) & TMASK;
        const unsigned g2 = (hx1 ^ r2) & TMASK, g3 = (hx1 ^ r3) & TMASK;
        float2 a0 = __ldg(&tab2[h0]), b0 = __ldg(&tab2[g0]);
        float2 a1 = __ldg(&tab2[h1]), b1 = __ldg(&tab2[g1]);
        float2 a2 = __ldg(&tab2[h2]), b2 = __ldg(&tab2[g2]);
        float2 a3 = __ldg(&tab2[h3]), b3 = __ldg(&tab2[g3]);
        e[0] = make_float4(a0.x, a0.y, b0.x, b0.y);
        e[1] = make_float4(a1.x, a1.y, b1.x, b1.y);
        e[2] = make_float4(a2.x, a2.y, b2.x, b2.y);
        e[3] = make_float4(a3.x, a3.y, b3.x, b3.y);
        meta4 = 0u;
    }
}

__device__ __forceinline__ void consume_level(
    const float4 e[4], unsigned meta4,
    float w0, float w1, float w2, float& a0, float& a1)
{
    const float u0 = 1.f - w0, u1 = 1.f - w1, u2 = 1.f - w2;
    float c[4];
    c[0] = u1 * u2; c[1] = u1 * w2; c[2] = w1 * u2; c[3] = w1 * w2;
    a0 = 0.f; a1 = 0.f;
#pragma unroll
    for (int k = 0; k < 4; ++k) {
        const bool sw = (meta4 >> k) & 1u;
        const float wA = c[k] * (sw ? w0 : u0);
        const float wB = c[k] * (sw ? u0 : w0);
        a0 = fmaf(wA, e[k].x, fmaf(wB, e[k].z, a0));
        a1 = fmaf(wA, e[k].y, fmaf(wB, e[k].w, a1));
    }
}

// ---- smem-cached level (levels 0..2): 8 LDS.64, nested-lerp trilinear ------
__device__ __forceinline__ bool cached_level(
    const float2* __restrict__ cache, int lo, int D, float invg,
    float X0, float X1, float X2, float& a0, float& a1)
{
    const float t0 = X0 * invg, t1 = X1 * invg, t2 = X2 * invg;
    const float f0 = floorf(t0), f1 = floorf(t1), f2 = floorf(t2);
    const float w0 = t0 - f0, w1 = t1 - f1, w2 = t2 - f2;
    const int c0 = (int)f0 - lo, c1 = (int)f1 - lo, c2 = (int)f2 - lo;
    if ((unsigned)c0 > (unsigned)(D - 2) ||
        (unsigned)c1 > (unsigned)(D - 2) ||
        (unsigned)c2 > (unsigned)(D - 2))
        return false;                      // out of cached range -> LDG fallback
    const int DD = D * D;
    const int base = (c0 * D + c1) * D + c2;
    const float2 e000 = cache[base],          e001 = cache[base + 1];
    const float2 e010 = cache[base + D],      e011 = cache[base + D + 1];
    const float2 e100 = cache[base + DD],     e101 = cache[base + DD + 1];
    const float2 e110 = cache[base + DD + D], e111 = cache[base + DD + D + 1];
    const float u0 = 1.f - w0, u1 = 1.f - w1, u2 = 1.f - w2;
    // lerp z, then y, then x — per channel
    const float zx00 = fmaf(w2, e001.x, u2 * e000.x);
    const float zx01 = fmaf(w2, e011.x, u2 * e010.x);
    const float zx10 = fmaf(w2, e101.x, u2 * e100.x);
    const float zx11 = fmaf(w2, e111.x, u2 * e110.x);
    const float zy00 = fmaf(w2, e001.y, u2 * e000.y);
    const float zy01 = fmaf(w2, e011.y, u2 * e010.y);
    const float zy10 = fmaf(w2, e101.y, u2 * e100.y);
    const float zy11 = fmaf(w2, e111.y, u2 * e110.y);
    const float yx0 = fmaf(w1, zx01, u1 * zx00);
    const float yx1 = fmaf(w1, zx11, u1 * zx10);
    const float yy0 = fmaf(w1, zy01, u1 * zy00);
    const float yy1 = fmaf(w1, zy11, u1 * zy10);
    a0 = fmaf(w0, yx1, u0 * yx0);
    a1 = fmaf(w0, yy1, u0 * yy0);
    return true;
}

__global__ void __launch_bounds__(TPB, 3)
ingp_hash_kernel(const float* __restrict__ x,
                 const float* __restrict__ emb,
                 float* __restrict__ out,
                 int n, Params P)
{
    extern __shared__ float smem[];
    float* stage = smem;                               // TPB*33 floats, pitch-33
    float2* cacheS = (float2*)(smem + STAGE_FLOATS);   // NDENSE float2

    const int tid = threadIdx.x;
    const int pid = blockIdx.x * TPB + tid;

    float x0 = 0.f, x1 = 0.f, x2 = 0.f;
    if (pid < n) {
        x0 = x[3 * pid + 0];
        x1 = x[3 * pid + 1];
        x2 = x[3 * pid + 2];
    }
    x0 = fminf(fmaxf(x0, -1.f), 1.f);
    x1 = fminf(fmaxf(x1, -1.f), 1.f);
    x2 = fminf(fmaxf(x2, -1.f), 1.f);
    const float X0 = x0 + 1.f, X1 = x1 + 1.f, X2 = x2 + 1.f;

    // prefill smem cache from the densified global copy (coalesced)
    for (int i = tid; i < NDENSE; i += TPB)
        cacheS[i] = __ldg(&g_dense[i]);

    // kick off the LDG pipeline for level 3 before the barrier so its latency
    // overlaps the cached-level LDS work
    float4 eb[STAGES][4];
    float w0b[STAGES], w1b[STAGES], w2b[STAGES];
    unsigned m0, m1, m2;
    load_level(emb, 3, P.invg[3], X0, X1, X2, eb[0], m0, w0b[0], w1b[0], w2b[0]);

    __syncthreads();

    // levels 0..2 from smem (with bit-identical LDG fallback if out of range
    // or geometry mismatch)
    {
        const int     los[3] = {LO0, LO1, LO2};
        const int     Ds[3]  = {D0, D1, D2};
        const int     offs[3]= {OFF0, OFF1, OFF2};
#pragma unroll
        for (int l = 0; l < 3; ++l) {
            float a0, a1;
            bool ok = false;
            if (P.cache_ok)
                ok = cached_level(cacheS + offs[l], los[l], Ds[l], P.invg[l],
                                  X0, X1, X2, a0, a1);
            if (!ok) {
                float4 ef[4]; unsigned mf; float fw0, fw1, fw2;
                load_level(emb, l, P.invg[l], X0, X1, X2, ef, mf, fw0, fw1, fw2);
                consume_level(ef, mf, fw0, fw1, fw2, a0, a1);
            }
            stage[tid * 33 + 2 * l + 0] = a0;
            stage[tid * 33 + 2 * l + 1] = a1;
        }
    }

    // fill the second pipeline stage, then run levels 3..15 (13 levels)
    load_level(emb, 4, P.invg[4], X0, X1, X2, eb[1], m1, w0b[1], w1b[1], w2b[1]);
    m2 = 0;
    unsigned mArr[STAGES] = {m0, m1, m2};

#pragma unroll
    for (int lvl = 3; lvl < NLEV; ++lvl) {
        const int cur = (lvl - 3) % STAGES;
        if (lvl + 2 < NLEV) {
            const int nxt = (lvl - 1) % STAGES;   // (lvl+2-3) % 3
            load_level(emb, lvl + 2, P.invg[lvl + 2], X0, X1, X2,
                       eb[nxt], mArr[nxt], w0b[nxt], w1b[nxt], w2b[nxt]);
        }
        float a0, a1;
        consume_level(eb[cur], mArr[cur], w0b[cur], w1b[cur], w2b[cur], a0, a1);
        stage[tid * 33 + 2 * lvl + 0] = a0;
        stage[tid * 33 + 2 * lvl + 1] = a1;
    }

    __syncthreads();

    // coalesced streaming write-out
    const long long base = (long long)blockIdx.x * (TPB * 32);
    const long long rem = (long long)n * 32 - base;
    const int lim = rem > (long long)(TPB * 32) ? (TPB * 32) : (int)rem;
    for (int i = tid; i < lim; i += TPB) {
        __stcs(&out[base + i], stage[(i >> 5) * 33 + (i & 31)]);
    }
}

extern "C" void kernel_launch(void* const* d_in, const int* in_sizes, int n_in,
                              void* d_out, int out_size)
{
    const float* x   = (const float*)d_in[0];
    const float* emb = (const float*)d_in[1];
    float* out = (float*)d_out;

    const int n = in_sizes[0] / 3;

    Params P;
    double resd[NLEV];
    {
        const double b = exp((log(512.0) - log(16.0)) / 15.0);
        for (int i = 0; i < NLEV; ++i) {
            resd[i] = floor(16.0 * pow(b, (double)i));
            P.invg[i] = (float)(resd[i] * 0.5);
        }
    }
    // cache geometry is hardcoded for res 16/20/25; verify, else disable cache
    P.cache_ok = ((int)resd[0] == 16 && (int)resd[1] == 20 && (int)resd[2] == 25) ? 1 : 0;

    static int attr_done_dummy = 0; // value unused; attribute set every call
    (void)attr_done_dummy;
    cudaFuncSetAttribute(ingp_hash_kernel,
                         cudaFuncAttributeMaxDynamicSharedMemorySize, SMEM_BYTES);

    if (P.cache_ok)
        build_dense<<<(NDENSE + 255) / 256, 256>>>(emb);

    const int grid = (n + TPB - 1) / TPB;
    ingp_hash_kernel<<<grid, TPB, SMEM_BYTES>>>(x, emb, out, n, P);
}